// round 11
// baseline (speedup 1.0000x reference)
#include <cuda_runtime.h>
#include <cstdint>

// GeometricStrideUnpool, round 8: R9 (ldmatrix tf32 GEMM, precomputed operands)
// with a 4-stage cp.async pipeline (wait_group 2) to cover gmem latency.
// 2 CTAs/SM (110 KB smem each).

#define THREADS 256
// smem layout (floats)
#define PA_OFF  0             // 4 x 2304: A tiles (64 x 36)
#define PB_OFF  9216          // 4 x 4608: B tiles (128 x 36)
#define TILE_A  2304
#define TILE_B  4608
#define SMEM_FLOATS 27648
#define SMEM_BYTES  (SMEM_FLOATS * 4)

// gmem scratch written by prep kernels every launch
__device__ float g_Mt [4u * 512 * 512];        // [ki][n][k] folded linear B, tf32
__device__ float g_PSt[512u * 1536];           // [n][si*512 + k] silu proj B, tf32
__device__ float g_Xt [4u * 2048 * 512];       // [b][l][k] x, tf32 (linear A)
__device__ float g_Gs [4u * 8192 * 1536];      // [ki][b*2048+l][si*512 + j] silu A, tf32

__device__ __forceinline__ uint32_t f2tf32(float f) {
    uint32_t r;
    asm("cvt.rna.tf32.f32 %0, %1;" : "=r"(r) : "f"(f));
    return r;
}

__device__ __forceinline__ void cp16(void* dst, const void* src) {
    uint32_t d = (uint32_t)__cvta_generic_to_shared(dst);
    asm volatile("cp.async.cg.shared.global [%0], [%1], 16;" :: "r"(d), "l"(src));
}

__device__ __forceinline__ void ldsm4(uint32_t* r, uint32_t addr) {
    asm volatile("ldmatrix.sync.aligned.m8n8.x4.shared.b16 {%0,%1,%2,%3}, [%4];"
                 : "=r"(r[0]), "=r"(r[1]), "=r"(r[2]), "=r"(r[3]) : "r"(addr));
}

__device__ __forceinline__ void mma_tf32(float* c, const uint32_t* a, uint32_t b0, uint32_t b1) {
    asm volatile(
        "mma.sync.aligned.m16n8k8.row.col.f32.tf32.tf32.f32 "
        "{%0,%1,%2,%3}, {%4,%5,%6,%7}, {%8,%9}, {%0,%1,%2,%3};"
        : "+f"(c[0]), "+f"(c[1]), "+f"(c[2]), "+f"(c[3])
        : "r"(a[0]), "r"(a[1]), "r"(a[2]), "r"(a[3]), "r"(b0), "r"(b1));
}

// ---------------- prep 1: fold linear part into M_ki (transposed tf32) ----------------
__global__ void prep_M(const float* __restrict__ proj, const float* __restrict__ W) {
    __shared__ float tile[32][33];
    const int ki = blockIdx.z;
    const int k0 = blockIdx.x * 32, n0 = blockIdx.y * 32;
    const int tx = threadIdx.x, ty = threadIdx.y;
    #pragma unroll
    for (int q = 0; q < 4; q++) {
        int kl = ty * 4 + q, k = k0 + kl, n = n0 + tx;
        float acc = 0.f;
        #pragma unroll
        for (int si = 0; si < 3; si++) {
            int s = 1 << si;
            int base = si * 1024;
            float p1 = proj[(size_t)(base + k) * 512 + n];
            float p2 = proj[(size_t)(base + ((k + s) & 511)) * 512 + n];
            float w1 = __ldg(W + ki * 512 + ((k - s) & 511));
            float w2 = __ldg(W + ki * 512 + ((k + s) & 511));
            acc += w1 * p1 - w2 * p2;
        }
        tile[kl][tx] = acc;
    }
    __syncthreads();
    #pragma unroll
    for (int q = 0; q < 4; q++) {
        int nl = ty * 4 + q, n = n0 + nl;
        ((uint32_t*)g_Mt)[(((size_t)ki * 512 + n) << 9) + k0 + tx] = f2tf32(tile[tx][nl]);
    }
}

// ---------------- prep 2: silu proj rows (transposed tf32) ----------------
__global__ void prep_PS(const float* __restrict__ proj) {
    __shared__ float tile[32][33];
    const int k0 = blockIdx.x * 32, n0 = blockIdx.y * 32;
    const int tx = threadIdx.x, ty = threadIdx.y;
    const int srow0 = 512 + (k0 >> 9) * 1024;
    #pragma unroll
    for (int q = 0; q < 4; q++) {
        int kl = ty * 4 + q, k = k0 + kl;
        tile[kl][tx] = proj[(size_t)(srow0 + (k & 511)) * 512 + n0 + tx];
    }
    __syncthreads();
    #pragma unroll
    for (int q = 0; q < 4; q++) {
        int nl = ty * 4 + q, n = n0 + nl;
        ((uint32_t*)g_PSt)[(size_t)n * 1536 + k0 + tx] = f2tf32(tile[tx][nl]);
    }
}

// ---------------- prep 3: x -> tf32 ----------------
__global__ void prep_X(const float* __restrict__ x) {
    size_t i = (size_t)blockIdx.x * 256 + threadIdx.x;   // float4 index, 1M total
    float4 v = ((const float4*)x)[i];
    uint32_t* dst = (uint32_t*)g_Xt + i * 4;
    dst[0] = f2tf32(v.x); dst[1] = f2tf32(v.y);
    dst[2] = f2tf32(v.z); dst[3] = f2tf32(v.w);
}

// ---------------- prep 4: silu A for all (ki, s), tf32 ----------------
__global__ void prep_G(const float* __restrict__ x, const float* __restrict__ W) {
    __shared__ float xrow[512];
    __shared__ float wsm[2048];
    const int row = blockIdx.x;                          // b*2048 + l, 8192 rows
    const int t = threadIdx.x;                           // 256
    xrow[t]       = x[(size_t)row * 512 + t];
    xrow[t + 256] = x[(size_t)row * 512 + t + 256];
    #pragma unroll
    for (int i = 0; i < 8; i++) wsm[t + 256 * i] = W[t + 256 * i];
    __syncthreads();
    #pragma unroll
    for (int ki = 0; ki < 4; ki++) {
        uint32_t* drow = (uint32_t*)g_Gs + ((size_t)ki * 8192 + row) * 1536;
        #pragma unroll
        for (int si = 0; si < 3; si++) {
            int s = 1 << si;
            #pragma unroll
            for (int jj = 0; jj < 2; jj++) {
                int j = t + 256 * jj;
                float sw = xrow[j] * wsm[ki * 512 + ((j - s) & 511)];
                float gv = sw * (1.0f / (1.0f + __expf(-sw)));
                drow[si * 512 + j] = f2tf32(gv);
            }
        }
    }
}

// ---------------- main GEMM kernel ----------------
__global__ void __launch_bounds__(THREADS, 2)
gsu8_kernel(const float* __restrict__ bias, float* __restrict__ out)
{
    extern __shared__ float sm[];

    const int t = threadIdx.x, warp = t >> 5, lane = t & 31;
    // n-tile fastest so A-sharing CTAs are co-resident
    const int nt   = blockIdx.x & 3;
    const int lt   = (blockIdx.x >> 2) & 31;
    const int b    = (blockIdx.x >> 7) & 3;
    const int ki   = blockIdx.x >> 9;
    const int l0   = lt << 6;
    const int n0   = nt << 7;
    const int vbase = l0 - 1 + ((ki == 3) ? 1 : 0);

    const int wm = warp >> 2, wn = warp & 3;             // 2 x 4 warp grid, 32x32 tiles
    const int gid = lane >> 2, tig = lane & 3;

    // ---- ldmatrix lane addresses (byte offsets within a tile) ----
    const int lgrp = lane >> 3, lr = lane & 7;
    uint32_t aoff[2], boff[2];
    #pragma unroll
    for (int mi = 0; mi < 2; mi++) {
        int row = wm * 32 + mi * 16 + (lgrp & 1) * 8 + lr;
        aoff[mi] = (uint32_t)((row * 36 + (lgrp >> 1) * 4) * 4);
    }
    #pragma unroll
    for (int p = 0; p < 2; p++) {
        int row = wn * 32 + p * 16 + (lgrp >> 1) * 8 + lr;
        boff[p] = (uint32_t)((row * 36 + (lgrp & 1) * 4) * 4);
    }
    uint32_t smb = (uint32_t)__cvta_generic_to_shared(sm);

    // ---- load lambdas ----
    auto loadB = [&](int c, float* dst) {                // 128n x 32k, stride 36
        const int grp = c >> 2, typ = c & 3;
        const float* src; size_t rs;
        if (typ == 0) { src = g_Mt + (((size_t)ki * 512 + n0) << 9) + (grp << 5); rs = 512; }
        else          { src = g_PSt + (size_t)n0 * 1536 + ((typ - 1) << 9) + (grp << 5); rs = 1536; }
        #pragma unroll
        for (int q = 0; q < 4; q++) {
            int idx = t + THREADS * q;                   // 0..1023
            int n = idx >> 3, c4 = idx & 7;
            cp16(dst + n * 36 + c4 * 4, src + (size_t)n * rs + c4 * 4);
        }
    };
    auto loadA = [&](int c, float* dst) {                // 64r x 32k, stride 36
        const int grp = c >> 2, typ = c & 3;
        const float* src; size_t rs;
        if (typ == 0) { src = g_Xt + ((size_t)b * 2048 + vbase) * 512 + (grp << 5); rs = 512; }
        else {
            src = g_Gs + ((size_t)ki * 8192 + b * 2048 + vbase) * 1536
                       + ((typ - 1) << 9) + (grp << 5);
            rs = 1536;
        }
        #pragma unroll
        for (int q = 0; q < 2; q++) {
            int idx = t + THREADS * q;                   // 0..511
            int r = idx >> 3, c4 = idx & 7;
            if (vbase + r >= 0) cp16(dst + r * 36 + c4 * 4, src + (size_t)r * rs + c4 * 4);
            else                *(float4*)(dst + r * 36 + c4 * 4) = make_float4(0.f, 0.f, 0.f, 0.f);
        }
    };

    float acc[2][4][4];
    #pragma unroll
    for (int i = 0; i < 2; i++)
        #pragma unroll
        for (int jv = 0; jv < 4; jv++)
            #pragma unroll
            for (int r = 0; r < 4; r++) acc[i][jv][r] = 0.f;

    auto mmaStep = [&](uint32_t aBase, uint32_t bBase) {
        #pragma unroll
        for (int ks = 0; ks < 4; ks++) {
            uint32_t a0[4], a1[4], p0[4], p1[4];
            ldsm4(a0, aBase + aoff[0] + ks * 32);
            ldsm4(a1, aBase + aoff[1] + ks * 32);
            ldsm4(p0, bBase + boff[0] + ks * 32);
            ldsm4(p1, bBase + boff[1] + ks * 32);
            mma_tf32(acc[0][0], a0, p0[0], p0[1]);
            mma_tf32(acc[0][1], a0, p0[2], p0[3]);
            mma_tf32(acc[0][2], a0, p1[0], p1[1]);
            mma_tf32(acc[0][3], a0, p1[2], p1[3]);
            mma_tf32(acc[1][0], a1, p0[0], p0[1]);
            mma_tf32(acc[1][1], a1, p0[2], p0[3]);
            mma_tf32(acc[1][2], a1, p1[0], p1[1]);
            mma_tf32(acc[1][3], a1, p1[2], p1[3]);
        }
    };

    // ---- prologue: preload chunks 0..2 ----
    #pragma unroll
    for (int c = 0; c < 3; c++) {
        loadB(c, sm + PB_OFF + c * TILE_B);
        loadA(c, sm + PA_OFF + c * TILE_A);
        asm volatile("cp.async.commit_group;");
    }

    // ---- main loop: 64 chunks, 4-stage pipeline, wait_group 2 ----
    #pragma unroll 1
    for (int it = 0; it < 64; ++it) {
        const int cur = it & 3;

        asm volatile("cp.async.wait_group 2;");
        __syncthreads();

        const int c3 = it + 3;
        if (c3 < 64) {
            const int s3 = c3 & 3;
            loadB(c3, sm + PB_OFF + s3 * TILE_B);
            loadA(c3, sm + PA_OFF + s3 * TILE_A);
        }
        asm volatile("cp.async.commit_group;");

        mmaStep(smb + (PA_OFF + cur * TILE_A) * 4,
                smb + (PB_OFF + cur * TILE_B) * 4);
    }

    // ---- epilogue ----
    {
        int rloc = wm * 32 + gid;                            // mi = 0
        size_t row1 = (size_t)b * 8192 + (size_t)(l0 + rloc) * 4 + ki;
        size_t row2 = row1 + 32;                             // +8 rows
        #pragma unroll
        for (int nb = 0; nb < 4; nb++) {
            int c = n0 + wn * 32 + nb * 8 + tig * 2;
            float b0 = __ldg(bias + c);
            float b1 = __ldg(bias + c + 1);
            *(float2*)(out + row1 * 512 + c) =
                make_float2(acc[0][nb][0] + b0, acc[0][nb][1] + b1);
            *(float2*)(out + row2 * 512 + c) =
                make_float2(acc[0][nb][2] + b0, acc[0][nb][3] + b1);
        }
    }
    {
        int rloc = wm * 32 + 16 + gid;                       // mi = 1
        size_t row1 = (size_t)b * 8192 + (size_t)(l0 + rloc) * 4 + ki;
        size_t row2 = row1 + 32;
        #pragma unroll
        for (int nb = 0; nb < 4; nb++) {
            int c = n0 + wn * 32 + nb * 8 + tig * 2;
            float b0 = __ldg(bias + c);
            float b1 = __ldg(bias + c + 1);
            *(float2*)(out + row1 * 512 + c) =
                make_float2(acc[1][nb][0] + b0, acc[1][nb][1] + b1);
            *(float2*)(out + row2 * 512 + c) =
                make_float2(acc[1][nb][2] + b0, acc[1][nb][3] + b1);
        }
    }
}

extern "C" void kernel_launch(void* const* d_in, const int* in_sizes, int n_in,
                              void* d_out, int out_size)
{
    const float* x    = (const float*)d_in[0];  // (4,1,2048,512)
    const float* W    = (const float*)d_in[1];  // (4,512)
    const float* proj = (const float*)d_in[2];  // (3072,512)
    const float* bias = (const float*)d_in[3];  // (512,)
    float* out = (float*)d_out;                 // (4,1,8192,512)

    prep_M <<<dim3(16, 16, 4), dim3(32, 8)>>>(proj, W);
    prep_PS<<<dim3(48, 16),    dim3(32, 8)>>>(proj);
    prep_X <<<4096, 256>>>(x);
    prep_G <<<8192, 256>>>(x, W);

    cudaFuncSetAttribute(gsu8_kernel,
                         cudaFuncAttributeMaxDynamicSharedMemorySize, SMEM_BYTES);
    gsu8_kernel<<<2048, THREADS, SMEM_BYTES>>>(bias, out);
}

// round 13
// speedup vs baseline: 1.3901x; 1.3901x over previous
#include <cuda_runtime.h>
#include <cstdint>

// GeometricStrideUnpool, round 9: 64x64 warp tiles to halve smem crossbar
// traffic (the measured limiter). CTA 128x128, 4 warps (128 thr), 3 CTAs/SM,
// 2-stage cp.async, ldmatrix tf32 fragments, fully precomputed operands.

#define THREADS 128
// smem layout (floats)
#define PA_OFF  0             // 2 x 4608: A tiles (128 x 36)
#define PB_OFF  9216          // 2 x 4608: B tiles (128 x 36)
#define TILE_A  4608
#define TILE_B  4608
#define SMEM_FLOATS 18432
#define SMEM_BYTES  (SMEM_FLOATS * 4)

// gmem scratch written by prep kernels every launch
__device__ float g_Mt [4u * 512 * 512];        // [ki][n][k] folded linear B, tf32
__device__ float g_PSt[512u * 1536];           // [n][si*512 + k] silu proj B, tf32
__device__ float g_Xt [4u * 2048 * 512];       // [b][l][k] x, tf32 (linear A)
__device__ float g_Gs [4u * 8192 * 1536];      // [ki][b*2048+l][si*512 + j] silu A, tf32

__device__ __forceinline__ uint32_t f2tf32(float f) {
    uint32_t r;
    asm("cvt.rna.tf32.f32 %0, %1;" : "=r"(r) : "f"(f));
    return r;
}

__device__ __forceinline__ void cp16(void* dst, const void* src) {
    uint32_t d = (uint32_t)__cvta_generic_to_shared(dst);
    asm volatile("cp.async.cg.shared.global [%0], [%1], 16;" :: "r"(d), "l"(src));
}

__device__ __forceinline__ void ldsm4(uint32_t* r, uint32_t addr) {
    asm volatile("ldmatrix.sync.aligned.m8n8.x4.shared.b16 {%0,%1,%2,%3}, [%4];"
                 : "=r"(r[0]), "=r"(r[1]), "=r"(r[2]), "=r"(r[3]) : "r"(addr));
}

__device__ __forceinline__ void mma_tf32(float* c, const uint32_t* a, uint32_t b0, uint32_t b1) {
    asm volatile(
        "mma.sync.aligned.m16n8k8.row.col.f32.tf32.tf32.f32 "
        "{%0,%1,%2,%3}, {%4,%5,%6,%7}, {%8,%9}, {%0,%1,%2,%3};"
        : "+f"(c[0]), "+f"(c[1]), "+f"(c[2]), "+f"(c[3])
        : "r"(a[0]), "r"(a[1]), "r"(a[2]), "r"(a[3]), "r"(b0), "r"(b1));
}

// ---------------- prep 1: fold linear part into M_ki (transposed tf32) ----------------
__global__ void prep_M(const float* __restrict__ proj, const float* __restrict__ W) {
    __shared__ float tile[32][33];
    const int ki = blockIdx.z;
    const int k0 = blockIdx.x * 32, n0 = blockIdx.y * 32;
    const int tx = threadIdx.x, ty = threadIdx.y;
    #pragma unroll
    for (int q = 0; q < 4; q++) {
        int kl = ty * 4 + q, k = k0 + kl, n = n0 + tx;
        float acc = 0.f;
        #pragma unroll
        for (int si = 0; si < 3; si++) {
            int s = 1 << si;
            int base = si * 1024;
            float p1 = proj[(size_t)(base + k) * 512 + n];
            float p2 = proj[(size_t)(base + ((k + s) & 511)) * 512 + n];
            float w1 = __ldg(W + ki * 512 + ((k - s) & 511));
            float w2 = __ldg(W + ki * 512 + ((k + s) & 511));
            acc += w1 * p1 - w2 * p2;
        }
        tile[kl][tx] = acc;
    }
    __syncthreads();
    #pragma unroll
    for (int q = 0; q < 4; q++) {
        int nl = ty * 4 + q, n = n0 + nl;
        ((uint32_t*)g_Mt)[(((size_t)ki * 512 + n) << 9) + k0 + tx] = f2tf32(tile[tx][nl]);
    }
}

// ---------------- prep 2: silu proj rows (transposed tf32) ----------------
__global__ void prep_PS(const float* __restrict__ proj) {
    __shared__ float tile[32][33];
    const int k0 = blockIdx.x * 32, n0 = blockIdx.y * 32;
    const int tx = threadIdx.x, ty = threadIdx.y;
    const int srow0 = 512 + (k0 >> 9) * 1024;
    #pragma unroll
    for (int q = 0; q < 4; q++) {
        int kl = ty * 4 + q, k = k0 + kl;
        tile[kl][tx] = proj[(size_t)(srow0 + (k & 511)) * 512 + n0 + tx];
    }
    __syncthreads();
    #pragma unroll
    for (int q = 0; q < 4; q++) {
        int nl = ty * 4 + q, n = n0 + nl;
        ((uint32_t*)g_PSt)[(size_t)n * 1536 + k0 + tx] = f2tf32(tile[tx][nl]);
    }
}

// ---------------- prep 3: x -> tf32 ----------------
__global__ void prep_X(const float* __restrict__ x) {
    size_t i = (size_t)blockIdx.x * 256 + threadIdx.x;   // float4 index, 1M total
    float4 v = ((const float4*)x)[i];
    uint32_t* dst = (uint32_t*)g_Xt + i * 4;
    dst[0] = f2tf32(v.x); dst[1] = f2tf32(v.y);
    dst[2] = f2tf32(v.z); dst[3] = f2tf32(v.w);
}

// ---------------- prep 4: silu A for all (ki, s), tf32 ----------------
__global__ void prep_G(const float* __restrict__ x, const float* __restrict__ W) {
    __shared__ float xrow[512];
    __shared__ float wsm[2048];
    const int row = blockIdx.x;                          // b*2048 + l, 8192 rows
    const int t = threadIdx.x;                           // 256
    xrow[t]       = x[(size_t)row * 512 + t];
    xrow[t + 256] = x[(size_t)row * 512 + t + 256];
    #pragma unroll
    for (int i = 0; i < 8; i++) wsm[t + 256 * i] = W[t + 256 * i];
    __syncthreads();
    #pragma unroll
    for (int ki = 0; ki < 4; ki++) {
        uint32_t* drow = (uint32_t*)g_Gs + ((size_t)ki * 8192 + row) * 1536;
        #pragma unroll
        for (int si = 0; si < 3; si++) {
            int s = 1 << si;
            #pragma unroll
            for (int jj = 0; jj < 2; jj++) {
                int j = t + 256 * jj;
                float sw = xrow[j] * wsm[ki * 512 + ((j - s) & 511)];
                float gv = sw * (1.0f / (1.0f + __expf(-sw)));
                drow[si * 512 + j] = f2tf32(gv);
            }
        }
    }
}

// ---------------- main GEMM kernel ----------------
__global__ void __launch_bounds__(THREADS, 3)
gsu9_kernel(const float* __restrict__ bias, float* __restrict__ out)
{
    extern __shared__ float sm[];

    const int t = threadIdx.x, warp = t >> 5, lane = t & 31;
    // n-tile fastest so A-sharing CTAs are co-resident
    const int nt   = blockIdx.x & 3;
    const int lt   = (blockIdx.x >> 2) & 15;
    const int b    = (blockIdx.x >> 6) & 3;
    const int ki   = blockIdx.x >> 8;
    const int l0   = lt << 7;                            // 128 l-rows per CTA
    const int n0   = nt << 7;
    const int vbase = l0 - 1 + ((ki == 3) ? 1 : 0);

    const int wm = warp >> 1, wn = warp & 1;             // 2 x 2 warp grid, 64x64 tiles
    const int gid = lane >> 2, tig = lane & 3;

    // ---- ldmatrix lane addresses (byte offsets within a tile) ----
    const int lgrp = lane >> 3, lr = lane & 7;
    uint32_t aoff[4], boff[4];
    #pragma unroll
    for (int mi = 0; mi < 4; mi++) {
        int row = wm * 64 + mi * 16 + (lgrp & 1) * 8 + lr;
        aoff[mi] = (uint32_t)((row * 36 + (lgrp >> 1) * 4) * 4);
    }
    #pragma unroll
    for (int p = 0; p < 4; p++) {
        int row = wn * 64 + p * 16 + (lgrp >> 1) * 8 + lr;
        boff[p] = (uint32_t)((row * 36 + (lgrp & 1) * 4) * 4);
    }
    uint32_t smb = (uint32_t)__cvta_generic_to_shared(sm);

    // ---- load lambdas (128 threads each) ----
    auto loadB = [&](int c, float* dst) {                // 128n x 32k, stride 36
        const int grp = c >> 2, typ = c & 3;
        const float* src; size_t rs;
        if (typ == 0) { src = g_Mt + (((size_t)ki * 512 + n0) << 9) + (grp << 5); rs = 512; }
        else          { src = g_PSt + (size_t)n0 * 1536 + ((typ - 1) << 9) + (grp << 5); rs = 1536; }
        #pragma unroll
        for (int q = 0; q < 8; q++) {
            int idx = t + THREADS * q;                   // 0..1023
            int n = idx >> 3, c4 = idx & 7;
            cp16(dst + n * 36 + c4 * 4, src + (size_t)n * rs + c4 * 4);
        }
    };
    auto loadA = [&](int c, float* dst) {                // 128r x 32k, stride 36
        const int grp = c >> 2, typ = c & 3;
        const float* src; size_t rs;
        if (typ == 0) { src = g_Xt + ((size_t)b * 2048 + vbase) * 512 + (grp << 5); rs = 512; }
        else {
            src = g_Gs + ((size_t)ki * 8192 + b * 2048 + vbase) * 1536
                       + ((typ - 1) << 9) + (grp << 5);
            rs = 1536;
        }
        #pragma unroll
        for (int q = 0; q < 8; q++) {
            int idx = t + THREADS * q;                   // 0..1023
            int r = idx >> 3, c4 = idx & 7;
            if (vbase + r >= 0) cp16(dst + r * 36 + c4 * 4, src + (size_t)r * rs + c4 * 4);
            else                *(float4*)(dst + r * 36 + c4 * 4) = make_float4(0.f, 0.f, 0.f, 0.f);
        }
    };

    float acc[4][8][4];
    #pragma unroll
    for (int i = 0; i < 4; i++)
        #pragma unroll
        for (int jv = 0; jv < 8; jv++)
            #pragma unroll
            for (int r = 0; r < 4; r++) acc[i][jv][r] = 0.f;

    auto mmaStep = [&](uint32_t aBase, uint32_t bBase) {
        #pragma unroll
        for (int ks = 0; ks < 4; ks++) {
            uint32_t a[4][4];
            #pragma unroll
            for (int mi = 0; mi < 4; mi++)
                ldsm4(a[mi], aBase + aoff[mi] + ks * 32);
            // B in two halves to bound live registers (acc128 + A16 + B8)
            #pragma unroll
            for (int h = 0; h < 2; h++) {
                uint32_t p0[4], p1[4];
                ldsm4(p0, bBase + boff[2 * h]     + ks * 32);
                ldsm4(p1, bBase + boff[2 * h + 1] + ks * 32);
                #pragma unroll
                for (int mi = 0; mi < 4; mi++) {
                    mma_tf32(acc[mi][4 * h + 0], a[mi], p0[0], p0[1]);
                    mma_tf32(acc[mi][4 * h + 1], a[mi], p0[2], p0[3]);
                    mma_tf32(acc[mi][4 * h + 2], a[mi], p1[0], p1[1]);
                    mma_tf32(acc[mi][4 * h + 3], a[mi], p1[2], p1[3]);
                }
            }
        }
    };

    // ---- prologue: chunk 0 ----
    loadB(0, sm + PB_OFF);
    loadA(0, sm + PA_OFF);
    asm volatile("cp.async.commit_group;");

    // ---- main loop: 64 chunks, 2-stage double buffer ----
    #pragma unroll 1
    for (int it = 0; it < 64; ++it) {
        const int cur = it & 1, nxt = cur ^ 1;

        asm volatile("cp.async.wait_group 0;");
        __syncthreads();

        if (it + 1 < 64) {
            loadB(it + 1, sm + PB_OFF + nxt * TILE_B);
            loadA(it + 1, sm + PA_OFF + nxt * TILE_A);
        }
        asm volatile("cp.async.commit_group;");

        mmaStep(smb + (PA_OFF + cur * TILE_A) * 4,
                smb + (PB_OFF + cur * TILE_B) * 4);
    }

    // ---- epilogue ----
    #pragma unroll
    for (int mi = 0; mi < 4; mi++) {
        int rloc = wm * 64 + mi * 16 + gid;
        size_t row1 = (size_t)b * 8192 + (size_t)(l0 + rloc) * 4 + ki;
        size_t row2 = row1 + 32;                             // +8 rows
        #pragma unroll
        for (int nb = 0; nb < 8; nb++) {
            int c = n0 + wn * 64 + nb * 8 + tig * 2;
            float b0 = __ldg(bias + c);
            float b1 = __ldg(bias + c + 1);
            *(float2*)(out + row1 * 512 + c) =
                make_float2(acc[mi][nb][0] + b0, acc[mi][nb][1] + b1);
            *(float2*)(out + row2 * 512 + c) =
                make_float2(acc[mi][nb][2] + b0, acc[mi][nb][3] + b1);
        }
    }
}

extern "C" void kernel_launch(void* const* d_in, const int* in_sizes, int n_in,
                              void* d_out, int out_size)
{
    const float* x    = (const float*)d_in[0];  // (4,1,2048,512)
    const float* W    = (const float*)d_in[1];  // (4,512)
    const float* proj = (const float*)d_in[2];  // (3072,512)
    const float* bias = (const float*)d_in[3];  // (512,)
    float* out = (float*)d_out;                 // (4,1,8192,512)

    prep_M <<<dim3(16, 16, 4), dim3(32, 8)>>>(proj, W);
    prep_PS<<<dim3(48, 16),    dim3(32, 8)>>>(proj);
    prep_X <<<4096, 256>>>(x);
    prep_G <<<8192, 256>>>(x, W);

    cudaFuncSetAttribute(gsu9_kernel,
                         cudaFuncAttributeMaxDynamicSharedMemorySize, SMEM_BYTES);
    gsu9_kernel<<<1024, THREADS, SMEM_BYTES>>>(bias, out);
}